// round 5
// baseline (speedup 1.0000x reference)
#include <cuda_runtime.h>
#include <cuda_fp16.h>
#include <cstdint>
#include <math.h>

// DeformAttn via ldmatrix + mma.sync (m16n8k16 fp16, fp32 accum) — base sm_103 ISA.
// Round 5: W pre-converted to swizzled fp16 in __device__ scratch (cp.async staging),
// D_TILE=32 with launch_bounds(256,2) -> 2 CTAs/SM, one barrier per sample.

namespace {
constexpr int Bn = 4, Cn = 128, Sn = 9, Dn = 16384;
constexpr int D_TILE = 32;
constexpr int NT = 256;
constexpr float ATT_SCALE = 0.25f;

constexpr int SM_WQ = 0;            // 3 x 32KB swizzled fp16 W
constexpr int SM_WK = 32768;
constexpr int SM_WV = 65536;
constexpr int SM_X0 = 98304;        // x tile [128c][32d] fp16, 8KB each
constexpr int SM_X1 = 106496;
constexpr int SM_TOTAL = 114688;    // 112KB -> 2 CTAs/SM
}

// W scratch: 3 matrices, 32KB each, in the exact swizzled smem byte layout
__device__ __align__(16) char g_wh[3 * 32768];

__device__ __forceinline__ uint32_t smem_u32(const void* p) {
    uint32_t a;
    asm("{ .reg .u64 t; cvta.to.shared.u64 t, %1; cvt.u32.u64 %0, t; }" : "=r"(a) : "l"(p));
    return a;
}
// W rows are 256B (128 halfwords); 16B chunks XOR-swizzled by row&7
__device__ __forceinline__ uint32_t swzW(int row, int colh) {
    int chunk = (colh >> 3) ^ (row & 7);
    return (uint32_t)(row * 256 + chunk * 16 + (colh & 7) * 2);
}
// x rows are 64B (32 halfwords); 16B chunks XOR-swizzled by (row>>1)&3
__device__ __forceinline__ uint32_t swzX(int row, int colh) {
    int chunk = ((colh >> 3) & 3) ^ ((row >> 1) & 3);
    return (uint32_t)(row * 64 + chunk * 16 + (colh & 7) * 2);
}
__device__ __forceinline__ void ldsm4(uint32_t r[4], uint32_t addr) {
    asm volatile("ldmatrix.sync.aligned.m8n8.x4.shared.b16 {%0,%1,%2,%3}, [%4];"
                 : "=r"(r[0]), "=r"(r[1]), "=r"(r[2]), "=r"(r[3]) : "r"(addr));
}
__device__ __forceinline__ void ldsm4t(uint32_t r[4], uint32_t addr) {
    asm volatile("ldmatrix.sync.aligned.m8n8.x4.trans.shared.b16 {%0,%1,%2,%3}, [%4];"
                 : "=r"(r[0]), "=r"(r[1]), "=r"(r[2]), "=r"(r[3]) : "r"(addr));
}
__device__ __forceinline__ void mma16816(float d[4], const uint32_t a[4], const uint32_t b[2]) {
    asm volatile(
        "mma.sync.aligned.m16n8k16.row.col.f32.f16.f16.f32 "
        "{%0,%1,%2,%3},{%4,%5,%6,%7},{%8,%9},{%0,%1,%2,%3};"
        : "+f"(d[0]), "+f"(d[1]), "+f"(d[2]), "+f"(d[3])
        : "r"(a[0]), "r"(a[1]), "r"(a[2]), "r"(a[3]), "r"(b[0]), "r"(b[1]));
}

// ---- prep kernel: W fp32 [o][c] -> swizzled fp16 scratch (runs once per launch) ----
__global__ void prep_w(const float* __restrict__ Wq, const float* __restrict__ Wk,
                       const float* __restrict__ Wv) {
    const int t = blockIdx.x * 256 + threadIdx.x;   // 0..12287
    const int w = t >> 12;
    const int rem = t & 4095;
    const int o = rem >> 5, f4 = rem & 31;
    const float* W = (w == 0) ? Wq : (w == 1) ? Wk : Wv;
    const float4 v = *reinterpret_cast<const float4*>(W + o * 128 + f4 * 4);
    char* dst = g_wh + w * 32768 + swzW(o, f4 * 4);
    *reinterpret_cast<__half2*>(dst)     = __floats2half2_rn(v.x, v.y);
    *reinterpret_cast<__half2*>(dst + 4) = __floats2half2_rn(v.z, v.w);
}

// ---- x staging: fp32 gmem -> swizzled fp16 smem, 4 float4 per thread ----
__device__ __forceinline__ void pf_load(float4 pf[4], const float* __restrict__ src,
                                        long cstride, int tid) {
#pragma unroll
    for (int i = 0; i < 4; i++) {
        const int g = i * 256 + tid;
        const int c = g >> 3, d4 = (g & 7) * 4;
        pf[i] = *reinterpret_cast<const float4*>(src + (long)c * cstride + d4);
    }
}
__device__ __forceinline__ void pf_store(char* xb, const float4 pf[4], int tid) {
#pragma unroll
    for (int i = 0; i < 4; i++) {
        const int g = i * 256 + tid;
        const int c = g >> 3, d4 = (g & 7) * 4;
        const uint32_t off = swzX(c, d4);
        *reinterpret_cast<__half2*>(xb + off)     = __floats2half2_rn(pf[i].x, pf[i].y);
        *reinterpret_cast<__half2*>(xb + off + 4) = __floats2half2_rn(pf[i].z, pf[i].w);
    }
}

// single projection (Q): warp tile 32o x 16d
__device__ __forceinline__ void proj(uint32_t wb, uint32_t xb, int warp_m, int warp_n,
                                     int lane, float acc[2][2][4]) {
#pragma unroll
    for (int t = 0; t < 2; t++)
#pragma unroll
        for (int n = 0; n < 2; n++)
#pragma unroll
            for (int i = 0; i < 4; i++) acc[t][n][i] = 0.0f;
#pragma unroll
    for (int ks = 0; ks < 8; ks++) {
        const int c0 = ks * 16;
        uint32_t a[2][4];
#pragma unroll
        for (int t = 0; t < 2; t++) {
            const int row = warp_m * 32 + t * 16 + (lane & 7) + ((lane >> 3) & 1) * 8;
            const int colh = c0 + (lane >> 4) * 8;
            ldsm4(a[t], wb + swzW(row, colh));
        }
        const int tl = lane >> 3;
        const int c = c0 + (tl & 1) * 8 + (lane & 7);
        const int d = warp_n * 16 + (tl >> 1) * 8;
        uint32_t r4[4];
        ldsm4t(r4, xb + swzX(c, d));
        uint32_t bf[2][2] = {{r4[0], r4[1]}, {r4[2], r4[3]}};
#pragma unroll
        for (int t = 0; t < 2; t++)
#pragma unroll
            for (int n = 0; n < 2; n++) mma16816(acc[t][n], a[t], bf[n]);
    }
}

// fused K+V projection sharing B fragments
__device__ __forceinline__ void proj2(uint32_t wbK, uint32_t wbV, uint32_t xb,
                                      int warp_m, int warp_n, int lane,
                                      float kp[2][2][4], float vp[2][2][4]) {
#pragma unroll
    for (int t = 0; t < 2; t++)
#pragma unroll
        for (int n = 0; n < 2; n++)
#pragma unroll
            for (int i = 0; i < 4; i++) { kp[t][n][i] = 0.0f; vp[t][n][i] = 0.0f; }
#pragma unroll
    for (int ks = 0; ks < 8; ks++) {
        const int c0 = ks * 16;
        uint32_t ak[2][4], av[2][4];
#pragma unroll
        for (int t = 0; t < 2; t++) {
            const int row = warp_m * 32 + t * 16 + (lane & 7) + ((lane >> 3) & 1) * 8;
            const int colh = c0 + (lane >> 4) * 8;
            const uint32_t so = swzW(row, colh);
            ldsm4(ak[t], wbK + so);
            ldsm4(av[t], wbV + so);
        }
        const int tl = lane >> 3;
        const int c = c0 + (tl & 1) * 8 + (lane & 7);
        const int d = warp_n * 16 + (tl >> 1) * 8;
        uint32_t r4[4];
        ldsm4t(r4, xb + swzX(c, d));
        uint32_t bf[2][2] = {{r4[0], r4[1]}, {r4[2], r4[3]}};
#pragma unroll
        for (int t = 0; t < 2; t++)
#pragma unroll
            for (int n = 0; n < 2; n++) {
                mma16816(kp[t][n], ak[t], bf[n]);
                mma16816(vp[t][n], av[t], bf[n]);
            }
    }
}

__global__ void __launch_bounds__(NT, 2)
deform_attn_hmma(const float* __restrict__ q,  const float* __restrict__ kv,
                 const float* __restrict__ bq, const float* __restrict__ bv,
                 float* __restrict__ out)
{
    extern __shared__ char smem[];
    const uint32_t sb = smem_u32(smem);
    const int tid = threadIdx.x, lane = tid & 31, wid = tid >> 5;
    const int warp_m = wid & 3, warp_n = wid >> 2;   // 4 x 2 warps
    const int b = blockIdx.y;
    const int dt = blockIdx.x * D_TILE;

    // ---- stage W (identity cp.async from pre-swizzled fp16 scratch) ----
#pragma unroll
    for (int i = 0; i < 24; i++) {
        const uint32_t dst = sb + (uint32_t)(tid * 16 + i * 4096);
        const char* src = g_wh + tid * 16 + i * 4096;
        asm volatile("cp.async.cg.shared.global [%0], [%1], 16;" :: "r"(dst), "l"(src));
    }
    asm volatile("cp.async.commit_group;" ::: "memory");

    // ---- stage q tile ----
    {
        float4 pf[4];
        pf_load(pf, q + (long)b * Cn * Dn + dt, (long)Dn, tid);
        pf_store(smem + SM_X0, pf, tid);
    }
    asm volatile("cp.async.wait_group 0;" ::: "memory");
    __syncthreads();

    // ---- Q projection (registers); add bq ----
    float qp[2][2][4];
    proj(sb + SM_WQ, sb + SM_X0, warp_m, warp_n, lane, qp);

    const int r0 = warp_m * 32 + (lane >> 2);
    {
        const float b0 = bq[r0], b1 = bq[r0 + 8], b2 = bq[r0 + 16], b3 = bq[r0 + 24];
#pragma unroll
        for (int n = 0; n < 2; n++) {
            qp[0][n][0] += b0; qp[0][n][1] += b0; qp[0][n][2] += b1; qp[0][n][3] += b1;
            qp[1][n][0] += b2; qp[1][n][1] += b2; qp[1][n][2] += b3; qp[1][n][3] += b3;
        }
    }

    float acc[2][2][4], den[2][2][2];
#pragma unroll
    for (int t = 0; t < 2; t++)
#pragma unroll
        for (int n = 0; n < 2; n++) {
            acc[t][n][0] = acc[t][n][1] = acc[t][n][2] = acc[t][n][3] = 0.0f;
            den[t][n][0] = den[t][n][1] = 0.0f;
        }

    __syncthreads();
    {
        float4 pf[4];
        pf_load(pf, kv + (long)(b * Cn) * Sn * Dn + dt, (long)Sn * Dn, tid);
        pf_store(smem + SM_X0, pf, tid);
    }
    __syncthreads();

    float4 pf[4];
    for (int s = 0; s < Sn; s++) {
        const uint32_t xb = sb + ((s & 1) ? SM_X1 : SM_X0);
        if (s + 1 < Sn)
            pf_load(pf, kv + ((long)(b * Cn) * Sn + (s + 1)) * Dn + dt, (long)Sn * Dn, tid);

        float kp[2][2][4], vp[2][2][4];
        proj2(sb + SM_WK, sb + SM_WV, xb, warp_m, warp_n, lane, kp, vp);

#pragma unroll
        for (int t = 0; t < 2; t++)
#pragma unroll
            for (int n = 0; n < 2; n++) {
                float pe = qp[t][n][0] * kp[t][n][0] + qp[t][n][2] * kp[t][n][2];
                float po = qp[t][n][1] * kp[t][n][1] + qp[t][n][3] * kp[t][n][3];
                pe += __shfl_xor_sync(0xffffffffu, pe, 4);
                pe += __shfl_xor_sync(0xffffffffu, pe, 8);
                pe += __shfl_xor_sync(0xffffffffu, pe, 16);
                po += __shfl_xor_sync(0xffffffffu, po, 4);
                po += __shfl_xor_sync(0xffffffffu, po, 8);
                po += __shfl_xor_sync(0xffffffffu, po, 16);
                const float we = __expf(ATT_SCALE * pe);
                const float wo = __expf(ATT_SCALE * po);
                den[t][n][0] += we; den[t][n][1] += wo;
                acc[t][n][0] = fmaf(we, vp[t][n][0], acc[t][n][0]);
                acc[t][n][1] = fmaf(wo, vp[t][n][1], acc[t][n][1]);
                acc[t][n][2] = fmaf(we, vp[t][n][2], acc[t][n][2]);
                acc[t][n][3] = fmaf(wo, vp[t][n][3], acc[t][n][3]);
            }

        // store s+1 into the buffer whose readers finished before the LAST barrier
        if (s + 1 < Sn)
            pf_store(smem + (((s + 1) & 1) ? SM_X1 : SM_X0), pf, tid);
        __syncthreads();
    }

    // ---- output: out = acc/den + bv (bv hoisted; weights sum to 1) ----
    {
        const float bv0 = bv[r0], bv1 = bv[r0 + 8], bv2 = bv[r0 + 16], bv3 = bv[r0 + 24];
        const float bvr[4] = {bv0, bv1, bv2, bv3};
#pragma unroll
        for (int t = 0; t < 2; t++)
#pragma unroll
            for (int n = 0; n < 2; n++) {
                const int row = warp_m * 32 + t * 16 + (lane >> 2);
                float* dst = out + ((long)(b * Cn + row)) * Dn + dt
                           + warp_n * 16 + n * 8 + (lane & 3) * 2;
                const float de = den[t][n][0], dz = den[t][n][1];
                float2 v0 = make_float2(acc[t][n][0] / de + bvr[t * 2],
                                        acc[t][n][1] / dz + bvr[t * 2]);
                float2 v1 = make_float2(acc[t][n][2] / de + bvr[t * 2 + 1],
                                        acc[t][n][3] / dz + bvr[t * 2 + 1]);
                *reinterpret_cast<float2*>(dst) = v0;
                *reinterpret_cast<float2*>(dst + (long)8 * Dn) = v1;
            }
    }
}

extern "C" void kernel_launch(void* const* d_in, const int* in_sizes, int n_in,
                              void* d_out, int out_size) {
    const float* q  = (const float*)d_in[0];
    const float* kv = (const float*)d_in[1];
    const float* Wq = (const float*)d_in[2];
    const float* bq = (const float*)d_in[3];
    const float* Wk = (const float*)d_in[4];
    // d_in[5] = bk: unused (softmax-invariant)
    const float* Wv = (const float*)d_in[6];
    const float* bv = (const float*)d_in[7];
    float* out = (float*)d_out;

    prep_w<<<48, 256>>>(Wq, Wk, Wv);

    cudaFuncSetAttribute(deform_attn_hmma,
                         cudaFuncAttributeMaxDynamicSharedMemorySize, SM_TOTAL);
    dim3 grid(Dn / D_TILE, Bn);   // 512 x 4 = 2048 blocks
    deform_attn_hmma<<<grid, NT, SM_TOTAL>>>(q, kv, bq, bv, out);
}

// round 6
// speedup vs baseline: 1.2931x; 1.2931x over previous
#include <cuda_runtime.h>
#include <cuda_fp16.h>
#include <cstdint>
#include <math.h>

// DeformAttn via ldmatrix + mma.sync (m16n8k16 fp16, fp32 accum) — base sm_103 ISA.
// Round 6: D_TILE=64 (revert R5), warp layout 8x1 (m16 = one head, n64):
// Wk/Wv A-fragments persistent in registers across all 9 samples -> hot-loop LDS
// is B-fragments only. W pre-swizzled fp16 via prep kernel + cp.async staging.

namespace {
constexpr int Bn = 4, Cn = 128, Sn = 9, Dn = 16384;
constexpr int D_TILE = 64;
constexpr int NT = 256;
constexpr float ATT_SCALE = 0.25f;

constexpr int SM_WQ = 0;            // 3 x 32KB swizzled fp16 W
constexpr int SM_WK = 32768;
constexpr int SM_WV = 65536;
constexpr int SM_X0 = 98304;        // x tile [128c][64d] fp16, 16KB each
constexpr int SM_X1 = 114688;
constexpr int SM_TOTAL = 131072;
}

// W scratch: 3 matrices, 32KB each, in the exact swizzled smem byte layout
__device__ __align__(16) char g_wh[3 * 32768];

__device__ __forceinline__ uint32_t smem_u32(const void* p) {
    uint32_t a;
    asm("{ .reg .u64 t; cvta.to.shared.u64 t, %1; cvt.u32.u64 %0, t; }" : "=r"(a) : "l"(p));
    return a;
}
// W rows are 256B (128 halfwords); 16B chunks XOR-swizzled by row&7
__device__ __forceinline__ uint32_t swzW(int row, int colh) {
    int chunk = (colh >> 3) ^ (row & 7);
    return (uint32_t)(row * 256 + chunk * 16 + (colh & 7) * 2);
}
// x rows are 128B (64 halfwords); 16B chunks XOR-swizzled by row&7
__device__ __forceinline__ uint32_t swzX(int row, int colh) {
    int chunk = (colh >> 3) ^ (row & 7);
    return (uint32_t)(row * 128 + chunk * 16 + (colh & 7) * 2);
}
__device__ __forceinline__ void ldsm4(uint32_t r[4], uint32_t addr) {
    asm volatile("ldmatrix.sync.aligned.m8n8.x4.shared.b16 {%0,%1,%2,%3}, [%4];"
                 : "=r"(r[0]), "=r"(r[1]), "=r"(r[2]), "=r"(r[3]) : "r"(addr));
}
__device__ __forceinline__ void ldsm4t(uint32_t r[4], uint32_t addr) {
    asm volatile("ldmatrix.sync.aligned.m8n8.x4.trans.shared.b16 {%0,%1,%2,%3}, [%4];"
                 : "=r"(r[0]), "=r"(r[1]), "=r"(r[2]), "=r"(r[3]) : "r"(addr));
}
__device__ __forceinline__ void mma16816(float d[4], const uint32_t a[4], const uint32_t b[2]) {
    asm volatile(
        "mma.sync.aligned.m16n8k16.row.col.f32.f16.f16.f32 "
        "{%0,%1,%2,%3},{%4,%5,%6,%7},{%8,%9},{%0,%1,%2,%3};"
        : "+f"(d[0]), "+f"(d[1]), "+f"(d[2]), "+f"(d[3])
        : "r"(a[0]), "r"(a[1]), "r"(a[2]), "r"(a[3]), "r"(b[0]), "r"(b[1]));
}

// ---- prep kernel: W fp32 [o][c] -> swizzled fp16 scratch ----
__global__ void prep_w(const float* __restrict__ Wq, const float* __restrict__ Wk,
                       const float* __restrict__ Wv) {
    const int t = blockIdx.x * 256 + threadIdx.x;   // 0..12287
    const int w = t >> 12;
    const int rem = t & 4095;
    const int o = rem >> 5, f4 = rem & 31;
    const float* W = (w == 0) ? Wq : (w == 1) ? Wk : Wv;
    const float4 v = *reinterpret_cast<const float4*>(W + o * 128 + f4 * 4);
    char* dst = g_wh + w * 32768 + swzW(o, f4 * 4);
    *reinterpret_cast<__half2*>(dst)     = __floats2half2_rn(v.x, v.y);
    *reinterpret_cast<__half2*>(dst + 4) = __floats2half2_rn(v.z, v.w);
}

// ---- x staging: one wave = 64 c-rows, 4 float4/thread ----
__device__ __forceinline__ void pf_load(float4 pf[4], const float* __restrict__ src,
                                        long cstride, int wave, int tid) {
#pragma unroll
    for (int i = 0; i < 4; i++) {
        const int g = i * 256 + tid;
        const int c = wave * 64 + (g >> 4), d4 = (g & 15) * 4;
        pf[i] = *reinterpret_cast<const float4*>(src + (long)c * cstride + d4);
    }
}
__device__ __forceinline__ void pf_store(char* xb, const float4 pf[4], int wave, int tid) {
#pragma unroll
    for (int i = 0; i < 4; i++) {
        const int g = i * 256 + tid;
        const int c = wave * 64 + (g >> 4), d4 = (g & 15) * 4;
        const uint32_t off = swzX(c, d4);
        *reinterpret_cast<__half2*>(xb + off)     = __floats2half2_rn(pf[i].x, pf[i].y);
        *reinterpret_cast<__half2*>(xb + off + 4) = __floats2half2_rn(pf[i].z, pf[i].w);
    }
}

__global__ void __launch_bounds__(NT, 1)
deform_attn_hmma(const float* __restrict__ q,  const float* __restrict__ kv,
                 const float* __restrict__ bq, const float* __restrict__ bv,
                 float* __restrict__ out)
{
    extern __shared__ char smem[];
    const uint32_t sb = smem_u32(smem);
    const int tid = threadIdx.x, lane = tid & 31, wid = tid >> 5;
    const int b = blockIdx.y;
    const int dt = blockIdx.x * D_TILE;

    // A-fragment ldsm address for this warp's m16 rows (row-block wid*16)
    const int a_row  = wid * 16 + (lane & 7) + ((lane >> 3) & 1) * 8;
    const int a_colq = (lane >> 4) * 8;
    // B-fragment ldsm4t base indices
    const int tl = lane >> 3;
    const int b_crem = (tl & 1) * 8 + (lane & 7);
    const int b_drem = (tl >> 1) * 8;

    // ---- stage all three W (identity cp.async from pre-swizzled fp16 scratch) ----
#pragma unroll
    for (int i = 0; i < 24; i++) {
        const uint32_t dst = sb + (uint32_t)(tid * 16 + i * 4096);
        const char* src = g_wh + tid * 16 + i * 4096;
        asm volatile("cp.async.cg.shared.global [%0], [%1], 16;" :: "r"(dst), "l"(src));
    }
    asm volatile("cp.async.commit_group;" ::: "memory");

    // ---- stage q tile (both waves) ----
    {
        float4 pf[4];
        pf_load(pf, q + (long)b * Cn * Dn + dt, (long)Dn, 0, tid);
        pf_store(smem + SM_X0, pf, 0, tid);
        pf_load(pf, q + (long)b * Cn * Dn + dt, (long)Dn, 1, tid);
        pf_store(smem + SM_X0, pf, 1, tid);
    }
    asm volatile("cp.async.wait_group 0;" ::: "memory");
    __syncthreads();

    // ---- persistent A fragments for Wk, Wv (32 regs each) ----
    uint32_t akK[8][4], akV[8][4];
#pragma unroll
    for (int ks = 0; ks < 8; ks++) {
        const int colh = ks * 16 + a_colq;
        ldsm4(akK[ks], sb + SM_WK + swzW(a_row, colh));
        ldsm4(akV[ks], sb + SM_WV + swzW(a_row, colh));
    }

    // ---- Q projection: m16 x n64 per warp ----
    float qp[8][4];
#pragma unroll
    for (int n = 0; n < 8; n++) qp[n][0] = qp[n][1] = qp[n][2] = qp[n][3] = 0.0f;
#pragma unroll
    for (int ks = 0; ks < 8; ks++) {
        uint32_t aq[4];
        ldsm4(aq, sb + SM_WQ + swzW(a_row, ks * 16 + a_colq));
        const int c = ks * 16 + b_crem;
#pragma unroll
        for (int nn = 0; nn < 4; nn++) {
            uint32_t r4[4];
            ldsm4t(r4, sb + SM_X0 + swzX(c, nn * 16 + b_drem));
            uint32_t b0[2] = {r4[0], r4[1]}, b1[2] = {r4[2], r4[3]};
            mma16816(qp[nn * 2],     aq, b0);
            mma16816(qp[nn * 2 + 1], aq, b1);
        }
    }

    const int r0 = wid * 16 + (lane >> 2);
    {
        const float b0 = bq[r0], b1 = bq[r0 + 8];
#pragma unroll
        for (int n = 0; n < 8; n++) {
            qp[n][0] += b0; qp[n][1] += b0; qp[n][2] += b1; qp[n][3] += b1;
        }
    }

    float acc[8][4], den[8][2];
#pragma unroll
    for (int n = 0; n < 8; n++) {
        acc[n][0] = acc[n][1] = acc[n][2] = acc[n][3] = 0.0f;
        den[n][0] = den[n][1] = 0.0f;
    }

    __syncthreads();   // Q-proj readers done with SM_X0
    {
        float4 pf[4];
        pf_load(pf, kv + (long)(b * Cn) * Sn * Dn + dt, (long)Sn * Dn, 0, tid);
        pf_store(smem + SM_X0, pf, 0, tid);
        pf_load(pf, kv + (long)(b * Cn) * Sn * Dn + dt, (long)Sn * Dn, 1, tid);
        pf_store(smem + SM_X0, pf, 1, tid);
    }
    __syncthreads();

    for (int s = 0; s < Sn; s++) {
        const uint32_t xb  = sb + ((s & 1) ? SM_X1 : SM_X0);
        char* nxt = smem + (((s + 1) & 1) ? SM_X1 : SM_X0);
        const float* nsrc = kv + ((long)(b * Cn) * Sn + (s + 1)) * Dn + dt;

        float4 pf[4];
        if (s + 1 < Sn) pf_load(pf, nsrc, (long)Sn * Dn, 0, tid);

        float kp[8][4], vp[8][4];
#pragma unroll
        for (int n = 0; n < 8; n++) {
            kp[n][0] = kp[n][1] = kp[n][2] = kp[n][3] = 0.0f;
            vp[n][0] = vp[n][1] = vp[n][2] = vp[n][3] = 0.0f;
        }

        // first half: ks 0..3 (c-rows 0..63)
#pragma unroll
        for (int ks = 0; ks < 4; ks++) {
            const int c = ks * 16 + b_crem;
#pragma unroll
            for (int nn = 0; nn < 4; nn++) {
                uint32_t r4[4];
                ldsm4t(r4, xb + swzX(c, nn * 16 + b_drem));
                uint32_t b0[2] = {r4[0], r4[1]}, b1[2] = {r4[2], r4[3]};
                mma16816(kp[nn * 2],     akK[ks], b0);
                mma16816(kp[nn * 2 + 1], akK[ks], b1);
                mma16816(vp[nn * 2],     akV[ks], b0);
                mma16816(vp[nn * 2 + 1], akV[ks], b1);
            }
        }

        if (s + 1 < Sn) {
            pf_store(nxt, pf, 0, tid);
            pf_load(pf, nsrc, (long)Sn * Dn, 1, tid);
        }

        // second half: ks 4..7
#pragma unroll
        for (int ks = 4; ks < 8; ks++) {
            const int c = ks * 16 + b_crem;
#pragma unroll
            for (int nn = 0; nn < 4; nn++) {
                uint32_t r4[4];
                ldsm4t(r4, xb + swzX(c, nn * 16 + b_drem));
                uint32_t b0[2] = {r4[0], r4[1]}, b1[2] = {r4[2], r4[3]};
                mma16816(kp[nn * 2],     akK[ks], b0);
                mma16816(kp[nn * 2 + 1], akK[ks], b1);
                mma16816(vp[nn * 2],     akV[ks], b0);
                mma16816(vp[nn * 2 + 1], akV[ks], b1);
            }
        }

        // softmax + weighted accumulate (head = this warp's 16 rows)
#pragma unroll
        for (int n = 0; n < 8; n++) {
            float pe = qp[n][0] * kp[n][0] + qp[n][2] * kp[n][2];
            float po = qp[n][1] * kp[n][1] + qp[n][3] * kp[n][3];
            pe += __shfl_xor_sync(0xffffffffu, pe, 4);
            pe += __shfl_xor_sync(0xffffffffu, pe, 8);
            pe += __shfl_xor_sync(0xffffffffu, pe, 16);
            po += __shfl_xor_sync(0xffffffffu, po, 4);
            po += __shfl_xor_sync(0xffffffffu, po, 8);
            po += __shfl_xor_sync(0xffffffffu, po, 16);
            const float we = __expf(ATT_SCALE * pe);
            const float wo = __expf(ATT_SCALE * po);
            den[n][0] += we; den[n][1] += wo;
            acc[n][0] = fmaf(we, vp[n][0], acc[n][0]);
            acc[n][1] = fmaf(wo, vp[n][1], acc[n][1]);
            acc[n][2] = fmaf(we, vp[n][2], acc[n][2]);
            acc[n][3] = fmaf(wo, vp[n][3], acc[n][3]);
        }

        if (s + 1 < Sn) pf_store(nxt, pf, 1, tid);
        __syncthreads();
    }

    // ---- output: out = acc/den + bv ----
    {
        const float bv0 = bv[r0], bv1 = bv[r0 + 8];
#pragma unroll
        for (int n = 0; n < 8; n++) {
            float* dst = out + ((long)(b * Cn + r0)) * Dn + dt + n * 8 + (lane & 3) * 2;
            const float de = den[n][0], dz = den[n][1];
            float2 v0 = make_float2(acc[n][0] / de + bv0, acc[n][1] / dz + bv0);
            float2 v1 = make_float2(acc[n][2] / de + bv1, acc[n][3] / dz + bv1);
            *reinterpret_cast<float2*>(dst) = v0;
            *reinterpret_cast<float2*>(dst + (long)8 * Dn) = v1;
        }
    }
}

extern "C" void kernel_launch(void* const* d_in, const int* in_sizes, int n_in,
                              void* d_out, int out_size) {
    const float* q  = (const float*)d_in[0];
    const float* kv = (const float*)d_in[1];
    const float* Wq = (const float*)d_in[2];
    const float* bq = (const float*)d_in[3];
    const float* Wk = (const float*)d_in[4];
    // d_in[5] = bk: unused (softmax-invariant)
    const float* Wv = (const float*)d_in[6];
    const float* bv = (const float*)d_in[7];
    float* out = (float*)d_out;

    prep_w<<<48, 256>>>(Wq, Wk, Wv);

    cudaFuncSetAttribute(deform_attn_hmma,
                         cudaFuncAttributeMaxDynamicSharedMemorySize, SM_TOTAL);
    dim3 grid(Dn / D_TILE, Bn);   // 256 x 4 = 1024 blocks
    deform_attn_hmma<<<grid, NT, SM_TOTAL>>>(q, kv, bq, bv, out);
}

// round 7
// speedup vs baseline: 1.6587x; 1.2827x over previous
#include <cuda_runtime.h>
#include <cuda_fp16.h>
#include <cstdint>
#include <math.h>

// DeformAttn via ldmatrix + mma.sync (m16n8k16 fp16, fp32 accum) — base sm_103 ISA.
// Round 7: R4 tile config (warp m32 x n32, D_TILE=64, 1 CTA/SM) +
//  - W pre-swizzled to fp16 scratch (prep kernel) staged via cp.async
//  - per-warpgroup x slices: each 128-thread group owns its 32-d half,
//    sample loop syncs with ONE named barrier (bar.sync id,128) per sample.

namespace {
constexpr int Bn = 4, Cn = 128, Sn = 9, Dn = 16384;
constexpr int D_TILE = 64;
constexpr int NT = 256;
constexpr float ATT_SCALE = 0.25f;

constexpr int SM_WQ = 0;            // 3 x 32KB swizzled fp16 W
constexpr int SM_WK = 32768;
constexpr int SM_WV = 65536;
constexpr int SM_X  = 98304;        // 4 slices: [buf][group] 8KB each = 32KB
constexpr int SM_TOTAL = 131072;
}

__device__ __align__(16) char g_wh[3 * 32768];

__device__ __forceinline__ uint32_t smem_u32(const void* p) {
    uint32_t a;
    asm("{ .reg .u64 t; cvta.to.shared.u64 t, %1; cvt.u32.u64 %0, t; }" : "=r"(a) : "l"(p));
    return a;
}
// W rows: 256B (128 halfwords), 16B chunks XOR-swizzled by row&7
__device__ __forceinline__ uint32_t swzW(int row, int colh) {
    int chunk = (colh >> 3) ^ (row & 7);
    return (uint32_t)(row * 256 + chunk * 16 + (colh & 7) * 2);
}
// x slice rows: 64B (32 halfwords), 16B chunks XOR-swizzled by (row>>1)&3
__device__ __forceinline__ uint32_t swzX(int row, int colh) {
    int chunk = ((colh >> 3) & 3) ^ ((row >> 1) & 3);
    return (uint32_t)(row * 64 + chunk * 16 + (colh & 7) * 2);
}
__device__ __forceinline__ void ldsm4(uint32_t r[4], uint32_t addr) {
    asm volatile("ldmatrix.sync.aligned.m8n8.x4.shared.b16 {%0,%1,%2,%3}, [%4];"
                 : "=r"(r[0]), "=r"(r[1]), "=r"(r[2]), "=r"(r[3]) : "r"(addr));
}
__device__ __forceinline__ void ldsm4t(uint32_t r[4], uint32_t addr) {
    asm volatile("ldmatrix.sync.aligned.m8n8.x4.trans.shared.b16 {%0,%1,%2,%3}, [%4];"
                 : "=r"(r[0]), "=r"(r[1]), "=r"(r[2]), "=r"(r[3]) : "r"(addr));
}
__device__ __forceinline__ void mma16816(float d[4], const uint32_t a[4], const uint32_t b[2]) {
    asm volatile(
        "mma.sync.aligned.m16n8k16.row.col.f32.f16.f16.f32 "
        "{%0,%1,%2,%3},{%4,%5,%6,%7},{%8,%9},{%0,%1,%2,%3};"
        : "+f"(d[0]), "+f"(d[1]), "+f"(d[2]), "+f"(d[3])
        : "r"(a[0]), "r"(a[1]), "r"(a[2]), "r"(a[3]), "r"(b[0]), "r"(b[1]));
}
__device__ __forceinline__ void grp_bar(int g) {
    asm volatile("bar.sync %0, 128;" :: "r"(g + 1) : "memory");
}

// ---- prep kernel: W fp32 [o][c] -> swizzled fp16 scratch ----
__global__ void prep_w(const float* __restrict__ Wq, const float* __restrict__ Wk,
                       const float* __restrict__ Wv) {
    const int t = blockIdx.x * 256 + threadIdx.x;   // 0..12287
    const int w = t >> 12;
    const int rem = t & 4095;
    const int o = rem >> 5, f4 = rem & 31;
    const float* W = (w == 0) ? Wq : (w == 1) ? Wk : Wv;
    const float4 v = *reinterpret_cast<const float4*>(W + o * 128 + f4 * 4);
    char* dst = g_wh + w * 32768 + swzW(o, f4 * 4);
    *reinterpret_cast<__half2*>(dst)     = __floats2half2_rn(v.x, v.y);
    *reinterpret_cast<__half2*>(dst + 4) = __floats2half2_rn(v.z, v.w);
}

// ---- per-group x slice staging: 128 threads stage [128c x 32d] fp32 -> fp16 ----
// src points at (c=0, d = slice base). 8 float4 per thread.
__device__ __forceinline__ void pf_load(float4 pf[8], const float* __restrict__ src,
                                        long cstride, int wt) {
#pragma unroll
    for (int i = 0; i < 8; i++) {
        const int g = i * 128 + wt;
        const int c = g >> 3, d4 = (g & 7) * 4;
        pf[i] = *reinterpret_cast<const float4*>(src + (long)c * cstride + d4);
    }
}
__device__ __forceinline__ void pf_store(char* xb, const float4 pf[8], int wt) {
#pragma unroll
    for (int i = 0; i < 8; i++) {
        const int g = i * 128 + wt;
        const int c = g >> 3, d4 = (g & 7) * 4;
        const uint32_t off = swzX(c, d4);
        *reinterpret_cast<__half2*>(xb + off)     = __floats2half2_rn(pf[i].x, pf[i].y);
        *reinterpret_cast<__half2*>(xb + off + 4) = __floats2half2_rn(pf[i].z, pf[i].w);
    }
}

// fused K+V projection: warp tile m32 x n32, B slice is [128c x 32d]
__device__ __forceinline__ void proj2(uint32_t wbK, uint32_t wbV, uint32_t xb,
                                      int warp_m, int lane,
                                      float kp[2][4][4], float vp[2][4][4]) {
#pragma unroll
    for (int t = 0; t < 2; t++)
#pragma unroll
        for (int n = 0; n < 4; n++)
#pragma unroll
            for (int i = 0; i < 4; i++) { kp[t][n][i] = 0.0f; vp[t][n][i] = 0.0f; }
#pragma unroll
    for (int ks = 0; ks < 8; ks++) {
        const int c0 = ks * 16;
        uint32_t ak[2][4], av[2][4];
#pragma unroll
        for (int t = 0; t < 2; t++) {
            const int row = warp_m * 32 + t * 16 + (lane & 7) + ((lane >> 3) & 1) * 8;
            const int colh = c0 + (lane >> 4) * 8;
            const uint32_t so = swzW(row, colh);
            ldsm4(ak[t], wbK + so);
            ldsm4(av[t], wbV + so);
        }
        const int tl = lane >> 3;
        const int c = c0 + (tl & 1) * 8 + (lane & 7);
        const int d = (tl >> 1) * 8;
        uint32_t bf[4][2];
#pragma unroll
        for (int np = 0; np < 2; np++) {
            uint32_t r4[4];
            ldsm4t(r4, xb + swzX(c, np * 16 + d));
            bf[np * 2][0] = r4[0]; bf[np * 2][1] = r4[1];
            bf[np * 2 + 1][0] = r4[2]; bf[np * 2 + 1][1] = r4[3];
        }
#pragma unroll
        for (int t = 0; t < 2; t++)
#pragma unroll
            for (int n = 0; n < 4; n++) {
                mma16816(kp[t][n], ak[t], bf[n]);
                mma16816(vp[t][n], av[t], bf[n]);
            }
    }
}
// single projection (Q only)
__device__ __forceinline__ void proj1(uint32_t wb, uint32_t xb, int warp_m, int lane,
                                      float acc[2][4][4]) {
#pragma unroll
    for (int t = 0; t < 2; t++)
#pragma unroll
        for (int n = 0; n < 4; n++)
#pragma unroll
            for (int i = 0; i < 4; i++) acc[t][n][i] = 0.0f;
#pragma unroll
    for (int ks = 0; ks < 8; ks++) {
        const int c0 = ks * 16;
        uint32_t a[2][4];
#pragma unroll
        for (int t = 0; t < 2; t++) {
            const int row = warp_m * 32 + t * 16 + (lane & 7) + ((lane >> 3) & 1) * 8;
            const int colh = c0 + (lane >> 4) * 8;
            ldsm4(a[t], wb + swzW(row, colh));
        }
        const int tl = lane >> 3;
        const int c = c0 + (tl & 1) * 8 + (lane & 7);
        const int d = (tl >> 1) * 8;
        uint32_t bf[4][2];
#pragma unroll
        for (int np = 0; np < 2; np++) {
            uint32_t r4[4];
            ldsm4t(r4, xb + swzX(c, np * 16 + d));
            bf[np * 2][0] = r4[0]; bf[np * 2][1] = r4[1];
            bf[np * 2 + 1][0] = r4[2]; bf[np * 2 + 1][1] = r4[3];
        }
#pragma unroll
        for (int t = 0; t < 2; t++)
#pragma unroll
            for (int n = 0; n < 4; n++) mma16816(acc[t][n], a[t], bf[n]);
    }
}

__global__ void __launch_bounds__(NT, 1)
deform_attn_hmma(const float* __restrict__ q,  const float* __restrict__ kv,
                 const float* __restrict__ bq, const float* __restrict__ bv,
                 float* __restrict__ out)
{
    extern __shared__ char smem[];
    const uint32_t sb = smem_u32(smem);
    const int tid = threadIdx.x, lane = tid & 31, wid = tid >> 5;
    const int warp_m = wid & 3;
    const int grp = wid >> 2;           // warpgroup: 0 -> d [0,32), 1 -> d [32,64)
    const int wt = tid & 127;           // thread id within group
    const int b = blockIdx.y;
    const int dt = blockIdx.x * D_TILE + grp * 32;   // this group's d base

    // slice buffers: [buf 0/1][group]
    char* xs0 = smem + SM_X + grp * 8192;
    char* xs1 = smem + SM_X + 16384 + grp * 8192;
    const uint32_t xb0 = sb + SM_X + grp * 8192;
    const uint32_t xb1 = xb0 + 16384;

    // ---- stage all three W via identity cp.async from pre-swizzled scratch ----
#pragma unroll
    for (int i = 0; i < 24; i++) {
        const uint32_t dst = sb + (uint32_t)(tid * 16 + i * 4096);
        const char* src = g_wh + tid * 16 + i * 4096;
        asm volatile("cp.async.cg.shared.global [%0], [%1], 16;" :: "r"(dst), "l"(src));
    }
    asm volatile("cp.async.commit_group;" ::: "memory");

    // ---- stage this group's q slice into buf0 ----
    {
        float4 pf[8];
        pf_load(pf, q + (long)b * Cn * Dn + dt, (long)Dn, wt);
        pf_store(xs0, pf, wt);
    }
    asm volatile("cp.async.wait_group 0;" ::: "memory");
    __syncthreads();   // W + q slices visible to everyone

    // ---- Q projection (warp m32 x group-slice n32) ----
    float qp[2][4][4];
    proj1(sb + SM_WQ, xb0, warp_m, lane, qp);

    const int r0 = warp_m * 32 + (lane >> 2);
    {
        const float b0 = bq[r0], b1 = bq[r0 + 8], b2 = bq[r0 + 16], b3 = bq[r0 + 24];
#pragma unroll
        for (int n = 0; n < 4; n++) {
            qp[0][n][0] += b0; qp[0][n][1] += b0; qp[0][n][2] += b1; qp[0][n][3] += b1;
            qp[1][n][0] += b2; qp[1][n][1] += b2; qp[1][n][2] += b3; qp[1][n][3] += b3;
        }
    }

    float acc[2][4][4], den[2][4][2];
#pragma unroll
    for (int t = 0; t < 2; t++)
#pragma unroll
        for (int n = 0; n < 4; n++) {
            acc[t][n][0] = acc[t][n][1] = acc[t][n][2] = acc[t][n][3] = 0.0f;
            den[t][n][0] = den[t][n][1] = 0.0f;
        }

    // ---- stage kv sample 0 into buf0 (group-local sync only) ----
    grp_bar(grp);   // group's Q-proj readers done with buf0
    {
        float4 pf[8];
        pf_load(pf, kv + (long)(b * Cn) * Sn * Dn + dt, (long)Sn * Dn, wt);
        pf_store(xs0, pf, wt);
    }
    grp_bar(grp);

    float4 pf[8];
    for (int s = 0; s < Sn; s++) {
        const uint32_t xb = (s & 1) ? xb1 : xb0;
        char* nxt = ((s + 1) & 1) ? xs1 : xs0;

        if (s + 1 < Sn)
            pf_load(pf, kv + ((long)(b * Cn) * Sn + (s + 1)) * Dn + dt, (long)Sn * Dn, wt);

        float kp[2][4][4], vp[2][4][4];
        proj2(sb + SM_WK, sb + SM_WV, xb, warp_m, lane, kp, vp);

#pragma unroll
        for (int t = 0; t < 2; t++)
#pragma unroll
            for (int n = 0; n < 4; n++) {
                float pe = qp[t][n][0] * kp[t][n][0] + qp[t][n][2] * kp[t][n][2];
                float po = qp[t][n][1] * kp[t][n][1] + qp[t][n][3] * kp[t][n][3];
                pe += __shfl_xor_sync(0xffffffffu, pe, 4);
                pe += __shfl_xor_sync(0xffffffffu, pe, 8);
                pe += __shfl_xor_sync(0xffffffffu, pe, 16);
                po += __shfl_xor_sync(0xffffffffu, po, 4);
                po += __shfl_xor_sync(0xffffffffu, po, 8);
                po += __shfl_xor_sync(0xffffffffu, po, 16);
                const float we = __expf(ATT_SCALE * pe);
                const float wo = __expf(ATT_SCALE * po);
                den[t][n][0] += we; den[t][n][1] += wo;
                acc[t][n][0] = fmaf(we, vp[t][n][0], acc[t][n][0]);
                acc[t][n][1] = fmaf(wo, vp[t][n][1], acc[t][n][1]);
                acc[t][n][2] = fmaf(we, vp[t][n][2], acc[t][n][2]);
                acc[t][n][3] = fmaf(wo, vp[t][n][3], acc[t][n][3]);
            }

        // write s+1 into the buffer whose readers finished before the LAST group barrier
        if (s + 1 < Sn) pf_store(nxt, pf, wt);
        grp_bar(grp);
    }

    // ---- output: out = acc/den + bv ----
    {
        const float bv0 = bv[r0], bv1 = bv[r0 + 8], bv2 = bv[r0 + 16], bv3 = bv[r0 + 24];
        const float bvr[4] = {bv0, bv1, bv2, bv3};
#pragma unroll
        for (int t = 0; t < 2; t++)
#pragma unroll
            for (int n = 0; n < 4; n++) {
                const int row = warp_m * 32 + t * 16 + (lane >> 2);
                float* dst = out + ((long)(b * Cn + row)) * Dn + dt + n * 8 + (lane & 3) * 2;
                const float de = den[t][n][0], dz = den[t][n][1];
                float2 v0 = make_float2(acc[t][n][0] / de + bvr[t * 2],
                                        acc[t][n][1] / dz + bvr[t * 2]);
                float2 v1 = make_float2(acc[t][n][2] / de + bvr[t * 2 + 1],
                                        acc[t][n][3] / dz + bvr[t * 2 + 1]);
                *reinterpret_cast<float2*>(dst) = v0;
                *reinterpret_cast<float2*>(dst + (long)8 * Dn) = v1;
            }
    }
}

extern "C" void kernel_launch(void* const* d_in, const int* in_sizes, int n_in,
                              void* d_out, int out_size) {
    const float* q  = (const float*)d_in[0];
    const float* kv = (const float*)d_in[1];
    const float* Wq = (const float*)d_in[2];
    const float* bq = (const float*)d_in[3];
    const float* Wk = (const float*)d_in[4];
    // d_in[5] = bk: unused (softmax-invariant)
    const float* Wv = (const float*)d_in[6];
    const float* bv = (const float*)d_in[7];
    float* out = (float*)d_out;

    prep_w<<<48, 256>>>(Wq, Wk, Wv);

    cudaFuncSetAttribute(deform_attn_hmma,
                         cudaFuncAttributeMaxDynamicSharedMemorySize, SM_TOTAL);
    dim3 grid(Dn / D_TILE, Bn);   // 256 x 4 = 1024 blocks
    deform_attn_hmma<<<grid, NT, SM_TOTAL>>>(q, kv, bq, bv, out);
}